// round 14
// baseline (speedup 1.0000x reference)
#include <cuda_runtime.h>
#include <math.h>

#define KNB 32
#define DD  128
#define FF  256
#define QMAX 32768

typedef unsigned long long u64;

// Scratch (static device arrays only — no allocs allowed)
__device__ float g_pooled[(size_t)QMAX * 2 * DD];   // [Q][256]: mean(128) | max(128)
__device__ float g_musig[(size_t)QMAX * 2];         // [Q][2]: mu, sigma

__device__ __forceinline__ float gelu_f(float x) {
    return 0.5f * x * (1.0f + erff(x * 0.70710678118654752440f));
}

__device__ __forceinline__ float warp_sum(float v) {
    #pragma unroll
    for (int off = 16; off; off >>= 1) v += __shfl_xor_sync(0xffffffffu, v, off);
    return v;
}

__device__ __forceinline__ u64 pack2(float lo, float hi) {
    u64 r;
    asm("mov.b64 %0, {%1, %2};" : "=l"(r) : "f"(lo), "f"(hi));
    return r;
}
__device__ __forceinline__ void unpack2(u64 v, float& lo, float& hi) {
    asm("mov.b64 {%0, %1}, %2;" : "=f"(lo), "=f"(hi) : "l"(v));
}
__device__ __forceinline__ u64 fma2(u64 a, u64 b, u64 c) {
    u64 d;
    asm("fma.rn.f32x2 %0, %1, %2, %3;" : "=l"(d) : "l"(a), "l"(b), "l"(c));
    return d;
}

// cp.async: 4-byte global->shared, bypasses the register file.
__device__ __forceinline__ void cp4(float* dst, const float* src) {
    unsigned d = (unsigned)__cvta_generic_to_shared(dst);
    asm volatile("cp.async.ca.shared.global [%0], [%1], 4;" :: "r"(d), "l"(src));
}
__device__ __forceinline__ void cp_commit() {
    asm volatile("cp.async.commit_group;" ::: "memory");
}
__device__ __forceinline__ void cp_wait_all() {
    asm volatile("cp.async.wait_group 0;" ::: "memory");
}

// Shared-memory layout (floats) — R13 structure + double weight buffer.
#define HT_STRIDE  36    // s_hT rows: [d][k]
#define X_STRIDE   36    // s_x  rows: [f][k]
#define W1T_STRIDE 258   // staged w1 chunk: [dj][f] (16 dj)
#define W2T_STRIDE 130   // staged w2 chunk: [fj][d] (16 fj)
#define WBUF       4128  // one weight buffer: 16*258 floats (w2 chunks fit too)

#define OFF_TOK 0                          // 128
#define OFF_HT  128                        // 128*36 = 4608
#define OFF_X   (OFF_HT + 128*HT_STRIDE)   // 4736; 256*36 = 9216
#define OFF_W   (OFF_X + 256*X_STRIDE)     // 13952; 2*4128 = 8256
#define OFF_PS  (OFF_W + 2*WBUF)           // 22208; 2*128 = 256
#define OFF_PM  (OFF_PS + 256)             // 22464; 2*128 = 256
#define SMEM_FLOATS (OFF_PM + 256)         // 22720
#define SMEM_BYTES  (SMEM_FLOATS * 4)      // 90880

// ---------------------------------------------------------------------------
// Kernel 1: per-query token pipeline + pooling. One block (256 thr) per query.
// R13 compute bodies; staging replaced by cp.async double-buffering.
// ---------------------------------------------------------------------------
__global__ __launch_bounds__(256) void field_main(
    const float* __restrict__ xyt_q, const float* __restrict__ obs_coords,
    const float* __restrict__ obs_vals, const int* __restrict__ nb_idx,
    const float* __restrict__ log_gammas,
    const float* __restrict__ w_in, const float* __restrict__ b_in,
    const float* __restrict__ ln1_g, const float* __restrict__ ln1_b,
    const float* __restrict__ w1, const float* __restrict__ b1,
    const float* __restrict__ w2, const float* __restrict__ b2,
    int Q)
{
    extern __shared__ float sm[];
    float* s_tok = sm + OFF_TOK;
    float* s_hT  = sm + OFF_HT;
    float* s_x   = sm + OFF_X;
    float* s_w   = sm + OFF_W;
    float* s_ps  = sm + OFF_PS;
    float* s_pm  = sm + OFF_PM;

    const int q = blockIdx.x;
    const int t = threadIdx.x;

    // --- 0. prefetch w1 chunk 0 into buf0 (hidden behind gather/GEMM0/LN) --
    {
        #pragma unroll
        for (int it = 0; it < 16; it++) {
            const int idx = t + it * 256;
            const int f  = idx >> 4;
            const int dj = idx & 15;
            cp4(s_w + dj * W1T_STRIDE + f, w1 + f * DD + dj);
        }
        cp_commit();
    }

    // --- 1. gather neighbors, token features, mu/sigma ---------------------
    if (t < 32) {
        const int k = t;
        const int idx = nb_idx[q * KNB + k];
        const float g0 = expf(log_gammas[0]);
        const float g1 = expf(log_gammas[1]);
        const float g2 = expf(log_gammas[2]);
        const float xq0 = xyt_q[q * 3 + 0];
        const float xq1 = xyt_q[q * 3 + 1];
        const float xq2 = xyt_q[q * 3 + 2];
        const float c0 = obs_coords[idx * 3 + 0];
        const float c1 = obs_coords[idx * 3 + 1];
        const float c2 = obs_coords[idx * 3 + 2];
        const float v  = obs_vals[idx];

        const float s1 = warp_sum(v);
        const float s2 = warp_sum(v * v);
        const float mu  = s1 * (1.0f / 32.0f);
        const float var = (s2 - 32.0f * mu * mu) * (1.0f / 31.0f);   // unbiased
        const float sig = fmaxf(sqrtf(fmaxf(var, 0.0f)), 1e-3f);

        s_tok[k * 4 + 0] = (c0 - xq0) * g0;
        s_tok[k * 4 + 1] = (c1 - xq1) * g1;
        s_tok[k * 4 + 2] = (c2 - xq2) * g2;
        s_tok[k * 4 + 3] = (v - mu) / sig;
        if (k == 0) { g_musig[q * 2 + 0] = mu; g_musig[q * 2 + 1] = sig; }
    }
    __syncthreads();

    // --- 2. GEMM0 (tok@w_in^T) + GELU + LN, stored transposed s_hT[d][k] ---
    {
        const int k = t >> 3;          // token 0..31 (8 threads per token)
        const int j = t & 7;           // d-lane 0..7
        const float4 tok = *reinterpret_cast<const float4*>(&s_tok[k * 4]);
        float hreg[16];
        float s1 = 0.0f, s2 = 0.0f;
        #pragma unroll
        for (int i = 0; i < 16; i++) {
            const int d = j + 8 * i;
            const float4 w = *reinterpret_cast<const float4*>(&w_in[d * 4]);
            float a = fmaf(tok.x, w.x,
                      fmaf(tok.y, w.y,
                      fmaf(tok.z, w.z,
                      fmaf(tok.w, w.w, b_in[d]))));
            const float hv = gelu_f(a);
            hreg[i] = hv;
            s1 += hv;
            s2 += hv * hv;
        }
        #pragma unroll
        for (int off = 1; off < 8; off <<= 1) {
            s1 += __shfl_xor_sync(0xffffffffu, s1, off);
            s2 += __shfl_xor_sync(0xffffffffu, s2, off);
        }
        const float mean = s1 * (1.0f / 128.0f);
        const float var  = s2 * (1.0f / 128.0f) - mean * mean;
        const float rstd = rsqrtf(var + 1e-5f);
        #pragma unroll
        for (int i = 0; i < 16; i++) {
            const int d = j + 8 * i;
            const float xn = (hreg[i] - mean) * rstd * ln1_g[d] + ln1_b[d];
            s_hT[d * HT_STRIDE + k] = xn;
        }
    }
    // s_hT writes ordered before GEMM1 reads by the first in-loop barrier

    // --- 3. GEMM1: x[f][k] = gelu(sum_d xn[d][k]*w1[f][d] + b1[f]), f = t --
    {
        const float bb = b1[t];
        u64 acc[16];
        #pragma unroll
        for (int kp = 0; kp < 16; kp++) acc[kp] = pack2(bb, bb);

        #pragma unroll 2
        for (int dc = 0; dc < 8; dc++) {
            cp_wait_all();          // chunk dc landed
            __syncthreads();        // all warps' copies + prior compute done

            if (dc < 7) {
                // issue w1 chunk dc+1 into the other buffer (overlaps compute)
                float* wdst = s_w + ((dc + 1) & 1) * WBUF;
                const float* wsrc = w1 + (dc + 1) * 16;
                #pragma unroll
                for (int it = 0; it < 16; it++) {
                    const int idx = t + it * 256;
                    const int f  = idx >> 4;
                    const int dj = idx & 15;
                    cp4(wdst + dj * W1T_STRIDE + f, wsrc + f * DD + dj);
                }
            } else {
                // last w1 chunk: prefetch w2 chunk 0 into buf0 instead
                #pragma unroll
                for (int it = 0; it < 8; it++) {
                    const int idx = t + it * 256;
                    const int dr = idx >> 4;
                    const int fj = idx & 15;
                    cp4(s_w + fj * W2T_STRIDE + dr, w2 + dr * FF + fj);
                }
            }
            cp_commit();

            const float* buf = s_w + (dc & 1) * WBUF;
            #pragma unroll
            for (int dj = 0; dj < 16; dj++) {
                const float wv = buf[dj * W1T_STRIDE + t];
                const u64 wp = pack2(wv, wv);
                const ulonglong2* xr = reinterpret_cast<const ulonglong2*>(
                    &s_hT[(dc * 16 + dj) * HT_STRIDE]);
                #pragma unroll
                for (int p2 = 0; p2 < 8; p2++) {
                    const ulonglong2 x2 = xr[p2];           // LDS.128 broadcast
                    acc[2 * p2 + 0] = fma2(x2.x, wp, acc[2 * p2 + 0]);
                    acc[2 * p2 + 1] = fma2(x2.y, wp, acc[2 * p2 + 1]);
                }
            }
        }
        // gelu + store transposed s_x[f][k]
        #pragma unroll
        for (int kp = 0; kp < 16; kp++) {
            float lo, hi;
            unpack2(acc[kp], lo, hi);
            lo = gelu_f(lo);
            hi = gelu_f(hi);
            *reinterpret_cast<u64*>(&s_x[t * X_STRIDE + 2 * kp]) = pack2(lo, hi);
        }
    }

    // --- 4. GEMM2: h2[d][k] = gelu(sum_f x[f][k]*w2[d][f] + b2[d]) --------
    {
        const int d  = t & 127;
        const int kh = t >> 7;          // token-pair half: kp 8*kh .. 8*kh+7
        const float bb = b2[d];
        u64 acc2[8];
        #pragma unroll
        for (int p = 0; p < 8; p++) acc2[p] = pack2(bb, bb);

        #pragma unroll 2
        for (int fc = 0; fc < 16; fc++) {
            cp_wait_all();          // chunk fc landed
            __syncthreads();        // also orders s_x stores before reads (fc=0)

            if (fc < 15) {
                float* wdst = s_w + ((fc + 1) & 1) * WBUF;
                const float* wsrc = w2 + (fc + 1) * 16;
                #pragma unroll
                for (int it = 0; it < 8; it++) {
                    const int idx = t + it * 256;
                    const int dr = idx >> 4;
                    const int fj = idx & 15;
                    cp4(wdst + fj * W2T_STRIDE + dr, wsrc + dr * FF + fj);
                }
            }
            cp_commit();            // empty group on the last iter is legal

            const float* buf = s_w + (fc & 1) * WBUF;
            #pragma unroll
            for (int fj = 0; fj < 16; fj++) {
                const float wv = buf[fj * W2T_STRIDE + d];
                const u64 wp = pack2(wv, wv);
                const ulonglong2* xr = reinterpret_cast<const ulonglong2*>(
                    &s_x[(fc * 16 + fj) * X_STRIDE + kh * 16]);
                #pragma unroll
                for (int p2 = 0; p2 < 4; p2++) {
                    const ulonglong2 x2 = xr[p2];           // LDS.128 broadcast
                    acc2[2 * p2 + 0] = fma2(x2.x, wp, acc2[2 * p2 + 0]);
                    acc2[2 * p2 + 1] = fma2(x2.y, wp, acc2[2 * p2 + 1]);
                }
            }
        }

        float s = 0.0f, m = -1e30f;
        #pragma unroll
        for (int p = 0; p < 8; p++) {
            float lo, hi;
            unpack2(acc2[p], lo, hi);
            lo = gelu_f(lo);
            hi = gelu_f(hi);
            s += lo + hi;
            m = fmaxf(m, fmaxf(lo, hi));
        }
        s_ps[kh * 128 + d] = s;
        s_pm[kh * 128 + d] = m;
    }
    __syncthreads();

    if (t < DD) {
        const float s = s_ps[t] + s_ps[128 + t];
        const float m = fmaxf(s_pm[t], s_pm[128 + t]);
        g_pooled[(size_t)q * 256 + t]      = s * (1.0f / 32.0f);
        g_pooled[(size_t)q * 256 + DD + t] = m;
    }
}

// ---------------------------------------------------------------------------
// Kernel 2: head. 32 queries per block, 256 threads.
// ---------------------------------------------------------------------------
__global__ __launch_bounds__(256) void field_head(
    const float* __restrict__ hln_g, const float* __restrict__ hln_b,
    const float* __restrict__ hw1, const float* __restrict__ hb1,
    const float* __restrict__ hw2, const float* __restrict__ hb2,
    float* __restrict__ out, int Q)
{
    __shared__ __align__(16) float s_p[32 * 256];
    __shared__ __align__(16) float s_w[256 * 9];
    __shared__ float s_red[8][32];

    const int qb = blockIdx.x * 32;
    const int t  = threadIdx.x;

    for (int idx = t; idx < 32 * 256; idx += 256) {
        const int qr = idx >> 8;
        s_p[idx] = (qb + qr < Q) ? g_pooled[(size_t)(qb + qr) * 256 + (idx & 255)] : 0.0f;
    }
    __syncthreads();

    // LN over 256 per query (ddof=0, eps=1e-5)
    {
        const int w = t >> 5, lane = t & 31;
        #pragma unroll
        for (int r = 0; r < 4; r++) {
            const int qr = w * 4 + r;
            float vals[8];
            float s1 = 0.0f, s2 = 0.0f;
            #pragma unroll
            for (int i = 0; i < 8; i++) {
                vals[i] = s_p[qr * 256 + lane + 32 * i];
                s1 += vals[i];
                s2 += vals[i] * vals[i];
            }
            s1 = warp_sum(s1);
            s2 = warp_sum(s2);
            const float mean = s1 * (1.0f / 256.0f);
            const float var  = s2 * (1.0f / 256.0f) - mean * mean;
            const float rstd = rsqrtf(var + 1e-5f);
            #pragma unroll
            for (int i = 0; i < 8; i++) {
                const int c = lane + 32 * i;
                s_p[qr * 256 + c] = (vals[i] - mean) * rstd * hln_g[c] + hln_b[c];
            }
        }
    }
    __syncthreads();

    float acc[32];
    #pragma unroll
    for (int qr = 0; qr < 32; qr++) acc[qr] = 0.0f;
    for (int cc = 0; cc < 32; cc++) {
        for (int idx = t; idx < 256 * 8; idx += 256) {
            const int r = idx >> 3, j = idx & 7;
            s_w[r * 9 + j] = hw1[r * 256 + cc * 8 + j];
        }
        __syncthreads();
        #pragma unroll
        for (int j4 = 0; j4 < 2; j4++) {
            const float w0 = s_w[t * 9 + j4 * 4 + 0];
            const float wa = s_w[t * 9 + j4 * 4 + 1];
            const float wb = s_w[t * 9 + j4 * 4 + 2];
            const float wc = s_w[t * 9 + j4 * 4 + 3];
            #pragma unroll
            for (int qr = 0; qr < 32; qr++) {
                const float4 pv = *reinterpret_cast<const float4*>(
                    &s_p[qr * 256 + cc * 8 + j4 * 4]);
                acc[qr] += pv.x * w0;
                acc[qr] += pv.y * wa;
                acc[qr] += pv.z * wb;
                acc[qr] += pv.w * wc;
            }
        }
        __syncthreads();
    }

    {
        const float bb  = hb1[t];
        const float w2f = hw2[t];
        #pragma unroll
        for (int qr = 0; qr < 32; qr++)
            acc[qr] = gelu_f(acc[qr] + bb) * w2f;
        #pragma unroll
        for (int qr = 0; qr < 32; qr++)
            acc[qr] = warp_sum(acc[qr]);
        const int w = t >> 5, lane = t & 31;
        s_red[w][lane] = acc[lane];
    }
    __syncthreads();

    if (t < 32) {
        const int qg = qb + t;
        if (qg < Q) {
            float tot = hb2[0];
            #pragma unroll
            for (int w = 0; w < 8; w++) tot += s_red[w][t];
            const float mu  = g_musig[(size_t)qg * 2 + 0];
            const float sig = g_musig[(size_t)qg * 2 + 1];
            out[qg] = tot * sig + mu;
        }
    }
}

// ---------------------------------------------------------------------------
extern "C" void kernel_launch(void* const* d_in, const int* in_sizes, int n_in,
                              void* d_out, int out_size)
{
    const float* xyt_q      = (const float*)d_in[0];
    const float* obs_coords = (const float*)d_in[1];
    const float* obs_vals   = (const float*)d_in[2];
    const int*   nb_idx     = (const int*)  d_in[3];
    const float* log_gammas = (const float*)d_in[4];
    const float* w_in       = (const float*)d_in[5];
    const float* b_in       = (const float*)d_in[6];
    const float* ln1_g      = (const float*)d_in[7];
    const float* ln1_b      = (const float*)d_in[8];
    const float* w1         = (const float*)d_in[9];
    const float* b1         = (const float*)d_in[10];
    const float* w2         = (const float*)d_in[11];
    const float* b2         = (const float*)d_in[12];
    const float* hln_g      = (const float*)d_in[13];
    const float* hln_b      = (const float*)d_in[14];
    const float* hw1        = (const float*)d_in[15];
    const float* hb1        = (const float*)d_in[16];
    const float* hw2        = (const float*)d_in[17];
    const float* hb2        = (const float*)d_in[18];
    float* out = (float*)d_out;

    const int Q = in_sizes[0] / 3;

    static bool attr_set = false;
    if (!attr_set) {
        cudaFuncSetAttribute(field_main,
                             cudaFuncAttributeMaxDynamicSharedMemorySize,
                             SMEM_BYTES);
        attr_set = true;
    }

    field_main<<<Q, 256, SMEM_BYTES>>>(xyt_q, obs_coords, obs_vals, nb_idx,
                                       log_gammas, w_in, b_in, ln1_g, ln1_b,
                                       w1, b1, w2, b2, Q);
    field_head<<<(Q + 31) / 32, 256>>>(hln_g, hln_b, hw1, hb1, hw2, hb2, out, Q);
}

// round 15
// speedup vs baseline: 1.0542x; 1.0542x over previous
#include <cuda_runtime.h>
#include <math.h>

#define KNB 32
#define DD  128
#define FF  256
#define QMAX 32768

typedef unsigned long long u64;

// Scratch (static device arrays only — no allocs allowed)
__device__ float g_pooled[(size_t)QMAX * 2 * DD];   // [Q][256]: mean(128) | max(128)
__device__ float g_musig[(size_t)QMAX * 2];         // [Q][2]: mu, sigma

__device__ __forceinline__ float gelu_f(float x) {
    return 0.5f * x * (1.0f + erff(x * 0.70710678118654752440f));
}

__device__ __forceinline__ float warp_sum(float v) {
    #pragma unroll
    for (int off = 16; off; off >>= 1) v += __shfl_xor_sync(0xffffffffu, v, off);
    return v;
}

__device__ __forceinline__ u64 pack2(float lo, float hi) {
    u64 r;
    asm("mov.b64 %0, {%1, %2};" : "=l"(r) : "f"(lo), "f"(hi));
    return r;
}
__device__ __forceinline__ void unpack2(u64 v, float& lo, float& hi) {
    asm("mov.b64 {%0, %1}, %2;" : "=f"(lo), "=f"(hi) : "l"(v));
}
__device__ __forceinline__ u64 fma2(u64 a, u64 b, u64 c) {
    u64 d;
    asm("fma.rn.f32x2 %0, %1, %2, %3;" : "=l"(d) : "l"(a), "l"(b), "l"(c));
    return d;
}

// Shared-memory layout (floats) — R13 layout (measured best).
#define HT_STRIDE  36    // s_hT rows: [d][k]
#define X_STRIDE   36    // s_x  rows: [f][k]
#define W1T_STRIDE 258   // staged w1 chunk: [dj][f] (16 dj)
#define W2T_STRIDE 130   // staged w2 chunk: [fj][d] (16 fj)

#define OFF_TOK 0                          // 128
#define OFF_HT  128                        // 128*36 = 4608
#define OFF_X   (OFF_HT + 128*HT_STRIDE)   // 4736; 256*36 = 9216
#define OFF_W   (OFF_X + 256*X_STRIDE)     // 13952; max(16*258, 16*130) = 4128
#define OFF_PS  (OFF_W + 16*W1T_STRIDE)    // 18080; 2*128 = 256
#define OFF_PM  (OFF_PS + 256)             // 18336; 2*128 = 256
#define SMEM_FLOATS (OFF_PM + 256)         // 18592
#define SMEM_BYTES  (SMEM_FLOATS * 4)      // 74368

// Empty parity-shift kernel: with 4 launches/call (pad, main, head, pad),
// ncu's fixed "-s 5 -c 1" window (6th launch == 2 mod 4) lands on field_main.
__global__ void pad_kernel() {}

// ---------------------------------------------------------------------------
// Kernel 1: per-query token pipeline + pooling. One block (256 thr) per query.
// ---------------------------------------------------------------------------
__global__ __launch_bounds__(256) void field_main(
    const float* __restrict__ xyt_q, const float* __restrict__ obs_coords,
    const float* __restrict__ obs_vals, const int* __restrict__ nb_idx,
    const float* __restrict__ log_gammas,
    const float* __restrict__ w_in, const float* __restrict__ b_in,
    const float* __restrict__ ln1_g, const float* __restrict__ ln1_b,
    const float* __restrict__ w1, const float* __restrict__ b1,
    const float* __restrict__ w2, const float* __restrict__ b2,
    int Q)
{
    extern __shared__ float sm[];
    float* s_tok = sm + OFF_TOK;
    float* s_hT  = sm + OFF_HT;
    float* s_x   = sm + OFF_X;
    float* s_w   = sm + OFF_W;
    float* s_ps  = sm + OFF_PS;
    float* s_pm  = sm + OFF_PM;

    const int q = blockIdx.x;
    const int t = threadIdx.x;

    // --- 1. gather neighbors, token features, mu/sigma ---------------------
    if (t < 32) {
        const int k = t;
        const int idx = nb_idx[q * KNB + k];
        const float g0 = expf(log_gammas[0]);
        const float g1 = expf(log_gammas[1]);
        const float g2 = expf(log_gammas[2]);
        const float xq0 = xyt_q[q * 3 + 0];
        const float xq1 = xyt_q[q * 3 + 1];
        const float xq2 = xyt_q[q * 3 + 2];
        const float c0 = obs_coords[idx * 3 + 0];
        const float c1 = obs_coords[idx * 3 + 1];
        const float c2 = obs_coords[idx * 3 + 2];
        const float v  = obs_vals[idx];

        const float s1 = warp_sum(v);
        const float s2 = warp_sum(v * v);
        const float mu  = s1 * (1.0f / 32.0f);
        const float var = (s2 - 32.0f * mu * mu) * (1.0f / 31.0f);   // unbiased
        const float sig = fmaxf(sqrtf(fmaxf(var, 0.0f)), 1e-3f);

        s_tok[k * 4 + 0] = (c0 - xq0) * g0;
        s_tok[k * 4 + 1] = (c1 - xq1) * g1;
        s_tok[k * 4 + 2] = (c2 - xq2) * g2;
        s_tok[k * 4 + 3] = (v - mu) / sig;
        if (k == 0) { g_musig[q * 2 + 0] = mu; g_musig[q * 2 + 1] = sig; }
    }
    __syncthreads();

    // --- 2. GEMM0 (tok@w_in^T) + GELU + LN, stored transposed s_hT[d][k] ---
    {
        const int k = t >> 3;          // token 0..31 (8 threads per token)
        const int j = t & 7;           // d-lane 0..7
        const float4 tok = *reinterpret_cast<const float4*>(&s_tok[k * 4]);
        float hreg[16];
        float s1 = 0.0f, s2 = 0.0f;
        #pragma unroll
        for (int i = 0; i < 16; i++) {
            const int d = j + 8 * i;
            const float4 w = *reinterpret_cast<const float4*>(&w_in[d * 4]);
            float a = fmaf(tok.x, w.x,
                      fmaf(tok.y, w.y,
                      fmaf(tok.z, w.z,
                      fmaf(tok.w, w.w, b_in[d]))));
            const float hv = gelu_f(a);
            hreg[i] = hv;
            s1 += hv;
            s2 += hv * hv;
        }
        #pragma unroll
        for (int off = 1; off < 8; off <<= 1) {
            s1 += __shfl_xor_sync(0xffffffffu, s1, off);
            s2 += __shfl_xor_sync(0xffffffffu, s2, off);
        }
        const float mean = s1 * (1.0f / 128.0f);
        const float var  = s2 * (1.0f / 128.0f) - mean * mean;
        const float rstd = rsqrtf(var + 1e-5f);
        #pragma unroll
        for (int i = 0; i < 16; i++) {
            const int d = j + 8 * i;
            const float xn = (hreg[i] - mean) * rstd * ln1_g[d] + ln1_b[d];
            s_hT[d * HT_STRIDE + k] = xn;
        }
    }
    // ordered by the first staging __syncthreads below

    // --- 3. GEMM1: x[f][k] = gelu(sum_d xn[d][k]*w1[f][d] + b1[f]), f = t --
    {
        const float bb = b1[t];
        u64 acc[16];
        #pragma unroll
        for (int kp = 0; kp < 16; kp++) acc[kp] = pack2(bb, bb);

        for (int dc = 0; dc < 8; dc++) {
            // stage w1 chunk transposed: s_w[dj][f]
            #pragma unroll
            for (int it = 0; it < 16; it++) {
                const int idx = t + it * 256;
                const int f  = idx >> 4;
                const int dj = idx & 15;
                s_w[dj * W1T_STRIDE + f] = w1[f * DD + dc * 16 + dj];
            }
            __syncthreads();
            #pragma unroll
            for (int dj = 0; dj < 16; dj++) {
                const float wv = s_w[dj * W1T_STRIDE + t];
                const u64 wp = pack2(wv, wv);
                const ulonglong2* xr = reinterpret_cast<const ulonglong2*>(
                    &s_hT[(dc * 16 + dj) * HT_STRIDE]);
                #pragma unroll
                for (int p2 = 0; p2 < 8; p2++) {
                    const ulonglong2 x2 = xr[p2];           // LDS.128 broadcast
                    acc[2 * p2 + 0] = fma2(x2.x, wp, acc[2 * p2 + 0]);
                    acc[2 * p2 + 1] = fma2(x2.y, wp, acc[2 * p2 + 1]);
                }
            }
            __syncthreads();
        }
        // gelu + store transposed s_x[f][k]
        #pragma unroll
        for (int kp = 0; kp < 16; kp++) {
            float lo, hi;
            unpack2(acc[kp], lo, hi);
            lo = gelu_f(lo);
            hi = gelu_f(hi);
            *reinterpret_cast<u64*>(&s_x[t * X_STRIDE + 2 * kp]) = pack2(lo, hi);
        }
    }

    // --- 4. GEMM2: h2[d][k] = gelu(sum_f x[f][k]*w2[d][f] + b2[d]) --------
    {
        const int d  = t & 127;
        const int kh = t >> 7;          // token-pair half: kp 8*kh .. 8*kh+7
        const float bb = b2[d];
        u64 acc2[8];
        #pragma unroll
        for (int p = 0; p < 8; p++) acc2[p] = pack2(bb, bb);

        for (int fc = 0; fc < 16; fc++) {
            // stage w2 chunk transposed: s_w[fj][d]
            #pragma unroll
            for (int it = 0; it < 8; it++) {
                const int idx = t + it * 256;
                const int dr = idx >> 4;
                const int fj = idx & 15;
                s_w[fj * W2T_STRIDE + dr] = w2[dr * FF + fc * 16 + fj];
            }
            __syncthreads();
            #pragma unroll
            for (int fj = 0; fj < 16; fj++) {
                const float wv = s_w[fj * W2T_STRIDE + d];
                const u64 wp = pack2(wv, wv);
                const ulonglong2* xr = reinterpret_cast<const ulonglong2*>(
                    &s_x[(fc * 16 + fj) * X_STRIDE + kh * 16]);
                #pragma unroll
                for (int p2 = 0; p2 < 4; p2++) {
                    const ulonglong2 x2 = xr[p2];           // LDS.128 broadcast
                    acc2[2 * p2 + 0] = fma2(x2.x, wp, acc2[2 * p2 + 0]);
                    acc2[2 * p2 + 1] = fma2(x2.y, wp, acc2[2 * p2 + 1]);
                }
            }
            __syncthreads();
        }
        float s = 0.0f, m = -1e30f;
        #pragma unroll
        for (int p = 0; p < 8; p++) {
            float lo, hi;
            unpack2(acc2[p], lo, hi);
            lo = gelu_f(lo);
            hi = gelu_f(hi);
            s += lo + hi;
            m = fmaxf(m, fmaxf(lo, hi));
        }
        s_ps[kh * 128 + d] = s;
        s_pm[kh * 128 + d] = m;
    }
    __syncthreads();

    if (t < DD) {
        const float s = s_ps[t] + s_ps[128 + t];
        const float m = fmaxf(s_pm[t], s_pm[128 + t]);
        g_pooled[(size_t)q * 256 + t]      = s * (1.0f / 32.0f);
        g_pooled[(size_t)q * 256 + DD + t] = m;
    }
}

// ---------------------------------------------------------------------------
// Kernel 2: head. 32 queries per block, 256 threads.
// ---------------------------------------------------------------------------
__global__ __launch_bounds__(256) void field_head(
    const float* __restrict__ hln_g, const float* __restrict__ hln_b,
    const float* __restrict__ hw1, const float* __restrict__ hb1,
    const float* __restrict__ hw2, const float* __restrict__ hb2,
    float* __restrict__ out, int Q)
{
    __shared__ __align__(16) float s_p[32 * 256];
    __shared__ __align__(16) float s_w[256 * 9];
    __shared__ float s_red[8][32];

    const int qb = blockIdx.x * 32;
    const int t  = threadIdx.x;

    for (int idx = t; idx < 32 * 256; idx += 256) {
        const int qr = idx >> 8;
        s_p[idx] = (qb + qr < Q) ? g_pooled[(size_t)(qb + qr) * 256 + (idx & 255)] : 0.0f;
    }
    __syncthreads();

    // LN over 256 per query (ddof=0, eps=1e-5)
    {
        const int w = t >> 5, lane = t & 31;
        #pragma unroll
        for (int r = 0; r < 4; r++) {
            const int qr = w * 4 + r;
            float vals[8];
            float s1 = 0.0f, s2 = 0.0f;
            #pragma unroll
            for (int i = 0; i < 8; i++) {
                vals[i] = s_p[qr * 256 + lane + 32 * i];
                s1 += vals[i];
                s2 += vals[i] * vals[i];
            }
            s1 = warp_sum(s1);
            s2 = warp_sum(s2);
            const float mean = s1 * (1.0f / 256.0f);
            const float var  = s2 * (1.0f / 256.0f) - mean * mean;
            const float rstd = rsqrtf(var + 1e-5f);
            #pragma unroll
            for (int i = 0; i < 8; i++) {
                const int c = lane + 32 * i;
                s_p[qr * 256 + c] = (vals[i] - mean) * rstd * hln_g[c] + hln_b[c];
            }
        }
    }
    __syncthreads();

    float acc[32];
    #pragma unroll
    for (int qr = 0; qr < 32; qr++) acc[qr] = 0.0f;
    for (int cc = 0; cc < 32; cc++) {
        for (int idx = t; idx < 256 * 8; idx += 256) {
            const int r = idx >> 3, j = idx & 7;
            s_w[r * 9 + j] = hw1[r * 256 + cc * 8 + j];
        }
        __syncthreads();
        #pragma unroll
        for (int j4 = 0; j4 < 2; j4++) {
            const float w0 = s_w[t * 9 + j4 * 4 + 0];
            const float wa = s_w[t * 9 + j4 * 4 + 1];
            const float wb = s_w[t * 9 + j4 * 4 + 2];
            const float wc = s_w[t * 9 + j4 * 4 + 3];
            #pragma unroll
            for (int qr = 0; qr < 32; qr++) {
                const float4 pv = *reinterpret_cast<const float4*>(
                    &s_p[qr * 256 + cc * 8 + j4 * 4]);
                acc[qr] += pv.x * w0;
                acc[qr] += pv.y * wa;
                acc[qr] += pv.z * wb;
                acc[qr] += pv.w * wc;
            }
        }
        __syncthreads();
    }

    {
        const float bb  = hb1[t];
        const float w2f = hw2[t];
        #pragma unroll
        for (int qr = 0; qr < 32; qr++)
            acc[qr] = gelu_f(acc[qr] + bb) * w2f;
        #pragma unroll
        for (int qr = 0; qr < 32; qr++)
            acc[qr] = warp_sum(acc[qr]);
        const int w = t >> 5, lane = t & 31;
        s_red[w][lane] = acc[lane];
    }
    __syncthreads();

    if (t < 32) {
        const int qg = qb + t;
        if (qg < Q) {
            float tot = hb2[0];
            #pragma unroll
            for (int w = 0; w < 8; w++) tot += s_red[w][t];
            const float mu  = g_musig[(size_t)qg * 2 + 0];
            const float sig = g_musig[(size_t)qg * 2 + 1];
            out[qg] = tot * sig + mu;
        }
    }
}

// ---------------------------------------------------------------------------
extern "C" void kernel_launch(void* const* d_in, const int* in_sizes, int n_in,
                              void* d_out, int out_size)
{
    const float* xyt_q      = (const float*)d_in[0];
    const float* obs_coords = (const float*)d_in[1];
    const float* obs_vals   = (const float*)d_in[2];
    const int*   nb_idx     = (const int*)  d_in[3];
    const float* log_gammas = (const float*)d_in[4];
    const float* w_in       = (const float*)d_in[5];
    const float* b_in       = (const float*)d_in[6];
    const float* ln1_g      = (const float*)d_in[7];
    const float* ln1_b      = (const float*)d_in[8];
    const float* w1         = (const float*)d_in[9];
    const float* b1         = (const float*)d_in[10];
    const float* w2         = (const float*)d_in[11];
    const float* b2         = (const float*)d_in[12];
    const float* hln_g      = (const float*)d_in[13];
    const float* hln_b      = (const float*)d_in[14];
    const float* hw1        = (const float*)d_in[15];
    const float* hb1        = (const float*)d_in[16];
    const float* hw2        = (const float*)d_in[17];
    const float* hb2        = (const float*)d_in[18];
    float* out = (float*)d_out;

    const int Q = in_sizes[0] / 3;

    static bool attr_set = false;
    if (!attr_set) {
        cudaFuncSetAttribute(field_main,
                             cudaFuncAttributeMaxDynamicSharedMemorySize,
                             SMEM_BYTES);
        attr_set = true;
    }

    // 4 launches per call: (pad, main, head, pad). ncu "-s 5 -c 1" profiles
    // the 6th launch == 2 (mod 4) == field_main, finally giving us a profile
    // of the kernel that is ~95% of runtime.
    pad_kernel<<<1, 32>>>();
    field_main<<<Q, 256, SMEM_BYTES>>>(xyt_q, obs_coords, obs_vals, nb_idx,
                                       log_gammas, w_in, b_in, ln1_g, ln1_b,
                                       w1, b1, w2, b2, Q);
    field_head<<<(Q + 31) / 32, 256>>>(hln_g, hln_b, hw1, hb1, hw2, hb2, out, Q);
    pad_kernel<<<1, 32>>>();
}